// round 16
// baseline (speedup 1.0000x reference)
#include <cuda_runtime.h>
#include <cuda_bf16.h>
#include <cuda_fp16.h>
#include <cstdint>

// Problem constants
#define BB    8
#define NN    2048
#define DIMM  512
#define HH    8
#define DD    64
#define INNERR 512
#define NSCALE 0.044194173824159216f   // 512^-0.5
#define LOG2E  1.4426950408889634f
#define QSCALE (NSCALE * LOG2E)        // folded so S is in log2 domain

// ---- warp MMA helpers (sm_80+ baseline; no arch-'a' gating) ----
__device__ __forceinline__ void ldsm4(uint32_t* r, uint32_t addr) {
    asm volatile("ldmatrix.sync.aligned.m8n8.x4.shared.b16 {%0,%1,%2,%3}, [%4];"
                 : "=r"(r[0]), "=r"(r[1]), "=r"(r[2]), "=r"(r[3]) : "r"(addr));
}
__device__ __forceinline__ void ldsm4t(uint32_t* r, uint32_t addr) {
    asm volatile("ldmatrix.sync.aligned.m8n8.x4.trans.shared.b16 {%0,%1,%2,%3}, [%4];"
                 : "=r"(r[0]), "=r"(r[1]), "=r"(r[2]), "=r"(r[3]) : "r"(addr));
}
__device__ __forceinline__ void mma16816h(float* c, const uint32_t* a, const uint32_t* b) {
    asm volatile("mma.sync.aligned.m16n8k16.row.col.f32.f16.f16.f32 "
                 "{%0,%1,%2,%3}, {%4,%5,%6,%7}, {%8,%9}, {%0,%1,%2,%3};"
                 : "+f"(c[0]), "+f"(c[1]), "+f"(c[2]), "+f"(c[3])
                 : "r"(a[0]), "r"(a[1]), "r"(a[2]), "r"(a[3]), "r"(b[0]), "r"(b[1]));
}
__device__ __forceinline__ uint32_t smem_to_u32(const void* p) {
    uint32_t a;
    asm("{ .reg .u64 t; cvta.to.shared.u64 t, %1; cvt.u32.u64 %0, t; }"
        : "=r"(a) : "l"(p));
    return a;
}
// ---- cp.async (LDGSTS) ----
__device__ __forceinline__ void cpa16(uint32_t dst, const void* src) {
    asm volatile("cp.async.cg.shared.global [%0], [%1], 16;" :: "r"(dst), "l"(src));
}
#define CP_COMMIT() asm volatile("cp.async.commit_group;" ::: "memory")
#define CP_WAIT(N)  asm volatile("cp.async.wait_group %0;" :: "n"(N) : "memory")

#define SWZ(off) ((off) ^ (((off) >> 3) & 0x70))

__device__ __forceinline__ uint32_t hf2pack(float lo, float hi) {
    __half2 t = __floats2half2_rn(lo, hi);
    return *reinterpret_cast<uint32_t*>(&t);
}

// =========================== scratch (device globals only) =================
#define ACNT ((size_t)16384 * 512)
__device__ unsigned short g_xf[ACNT];               // x fp16
__device__ unsigned short g_mf[ACNT];               // m fp16
__device__ unsigned short g_of[ACNT];               // attention out fp16 [b,n,(h d)]
#define QKV ((size_t)BB * HH * NN * DD)
__device__ unsigned short g_qf[QKV];                // Q*qscale fp16 [b,h,n,d]
__device__ unsigned short g_kf[QKV];                // K fp16
__device__ unsigned short g_vf[QKV];                // V fp16
#define WCNT ((size_t)512 * 512)
__device__ unsigned short g_wqf[WCNT];              // Wq^T fp16
__device__ unsigned short g_wkf[WCNT];              // Wk^T fp16
__device__ unsigned short g_wvf[WCNT];              // Wv^T fp16
__device__ unsigned short g_woh[WCNT], g_wol[WCNT]; // Wo^T fp16 hi/lo

// ---------------------------------------------------------------------------
// cvtA: fp32 [16384,512] -> fp16. blockIdx.y selects x / m.
// ---------------------------------------------------------------------------
__global__ __launch_bounds__(256)
void cvtA(const float* __restrict__ x, const float* __restrict__ m)
{
    const float* src = blockIdx.y ? m : x;
    unsigned short* d = blockIdx.y ? g_mf : g_xf;
    size_t i4 = (size_t)blockIdx.x * 256 + threadIdx.x;
    float4 v = ((const float4*)src)[i4];
    uint2 o;
    o.x = hf2pack(v.x, v.y);
    o.y = hf2pack(v.z, v.w);
    ((uint2*)d)[i4] = o;
}

// ---------------------------------------------------------------------------
// cvtW: all 4 weights, blockIdx.z selects. z<3 -> fp16 transposed plane;
// z==3 -> Wo fp16 hi/lo transposed planes.
// ---------------------------------------------------------------------------
__global__ __launch_bounds__(1024)
void cvtW(const float* __restrict__ Wq, const float* __restrict__ Wk,
          const float* __restrict__ Wv, const float* __restrict__ Wo)
{
    const int z = blockIdx.z;
    const float* W = (z == 0) ? Wq : (z == 1) ? Wk : (z == 2) ? Wv : Wo;
    __shared__ float tile[32][33];
    int k = blockIdx.y * 32 + threadIdx.y;
    int n = blockIdx.x * 32 + threadIdx.x;
    tile[threadIdx.y][threadIdx.x] = W[(size_t)k * 512 + n];
    __syncthreads();
    int nn = blockIdx.x * 32 + threadIdx.y;
    int kk = blockIdx.y * 32 + threadIdx.x;
    float v = tile[threadIdx.x][threadIdx.y];
    size_t idx = (size_t)nn * 512 + kk;
    if (z < 3) {
        unsigned short* d = (z == 0) ? g_wqf : (z == 1) ? g_wkf : g_wvf;
        d[idx] = __half_as_ushort(__float2half_rn(v));
    } else {
        __half hh = __float2half_rn(v);
        float r = v - __half2float(hh);
        g_woh[idx] = __half_as_ushort(hh);
        g_wol[idx] = __half_as_ushort(__float2half_rn(r));
    }
}

// ---------------------------------------------------------------------------
// Fused QKV projection GEMM: grid (12, 128).
// col-blocks 0-3: Q = x @ Wq * QSCALE; 4-7: K = m @ Wk; 8-11: V = m @ Wv.
// Block 128x128, 8 warps, 2-stage cp.async (stage = 32KB). fp16 out, head-split.
// ---------------------------------------------------------------------------
#define GF_SA 0
#define GF_SB 16384
#define GF_STAGE 32768
#define GF_SMEM (2 * GF_STAGE)

__global__ __launch_bounds__(256)
void gemm_qkv()
{
    const int sel = blockIdx.x >> 2;        // 0=Q 1=K 2=V
    const int cb  = blockIdx.x & 3;         // col block within 512
    const unsigned short* A = (sel == 0) ? g_xf : g_mf;
    const unsigned short* B = (sel == 0) ? g_wqf : (sel == 1) ? g_wkf : g_wvf;
    unsigned short* Cf = (sel == 0) ? g_qf : (sel == 1) ? g_kf : g_vf;

    extern __shared__ char smem[];
    const uint32_t sb = smem_to_u32(smem);

    const int tid  = threadIdx.x;
    const int wid  = tid >> 5;
    const int lane = tid & 31;
    const int warp_m = wid >> 2;
    const int warp_n = wid & 3;
    const int rowBase = blockIdx.y * 128;
    const int colBase = cb * 128;

    float c[4][4][4];
#pragma unroll
    for (int i = 0; i < 4; ++i)
#pragma unroll
        for (int j = 0; j < 4; ++j)
#pragma unroll
            for (int e = 0; e < 4; ++e) c[i][j][e] = 0.f;

    uint32_t aAddr[4], maskA[4];
    {
        int r = lane & 15, hf = lane >> 4;
#pragma unroll
        for (int mt = 0; mt < 4; ++mt) {
            uint32_t rb = (uint32_t)((warp_m * 64 + mt * 16 + r) * 128 + hf * 16);
            maskA[mt] = (rb >> 3) & 0x70;
            aAddr[mt] = rb;
        }
    }
    uint32_t bAddr[2], maskB[2];
    {
        int rn = ((lane >> 4) << 3) + (lane & 7);
        int hf = (lane >> 3) & 1;
#pragma unroll
        for (int nt2 = 0; nt2 < 2; ++nt2) {
            uint32_t rb = (uint32_t)((warp_n * 32 + nt2 * 16 + rn) * 128 + hf * 16);
            maskB[nt2] = (rb >> 3) & 0x70;
            bAddr[nt2] = rb;
        }
    }

    auto load_stage = [&](int st, int kc) {
        uint32_t base = sb + st * GF_STAGE;
#pragma unroll
        for (int it = 0; it < 4; ++it) {
            int unit = it * 256 + tid;
            int row = unit >> 3, seg = unit & 7;
            uint32_t off = SWZ((uint32_t)(row * 128 + seg * 16));
            cpa16(base + GF_SA + off, A + (size_t)(rowBase + row) * 512 + kc * 64 + seg * 8);
            cpa16(base + GF_SB + off, B + (size_t)(colBase + row) * 512 + kc * 64 + seg * 8);
        }
    };

    load_stage(0, 0);
    CP_COMMIT();

    for (int kc = 0; kc < 8; ++kc) {
        if (kc + 1 < 8) {
            load_stage((kc + 1) & 1, kc + 1);
            CP_COMMIT();
            CP_WAIT(1);
        } else {
            CP_WAIT(0);
        }
        __syncthreads();

        const uint32_t stb = sb + (kc & 1) * GF_STAGE;
#pragma unroll
        for (int ks = 0; ks < 4; ++ks) {
            uint32_t af[4][4], bf[4][2];
#pragma unroll
            for (int mt = 0; mt < 4; ++mt)
                ldsm4(af[mt], stb + GF_SA + ((aAddr[mt] + ks * 32) ^ maskA[mt]));
#pragma unroll
            for (int nt2 = 0; nt2 < 2; ++nt2) {
                uint32_t t4[4];
                ldsm4(t4, stb + GF_SB + ((bAddr[nt2] + ks * 32) ^ maskB[nt2]));
                bf[2 * nt2][0] = t4[0]; bf[2 * nt2][1] = t4[1];
                bf[2 * nt2 + 1][0] = t4[2]; bf[2 * nt2 + 1][1] = t4[3];
            }
#pragma unroll
            for (int mt = 0; mt < 4; ++mt)
#pragma unroll
                for (int nt = 0; nt < 4; ++nt)
                    mma16816h(c[mt][nt], af[mt], bf[nt]);
        }
        __syncthreads();
    }

    const int r0 = (lane >> 2);
    const int c2 = 2 * (lane & 3);
    const float s = (sel == 0) ? QSCALE : 1.f;
#pragma unroll
    for (int mt = 0; mt < 4; ++mt) {
#pragma unroll
        for (int nt = 0; nt < 4; ++nt) {
            int row = rowBase + warp_m * 64 + mt * 16 + r0;
            int col = colBase + warp_n * 32 + nt * 8 + c2;
            const int h = col >> 6, d0 = col & 63;
#pragma unroll
            for (int half = 0; half < 2; ++half) {
                const int rw = row + half * 8;
                const int b = rw >> 11, n = rw & 2047;
                size_t idx = (((size_t)(b * HH + h) * NN + n) * DD + d0) >> 1;
                ((uint32_t*)Cf)[idx] = hf2pack(c[mt][nt][2 * half + 0] * s,
                                               c[mt][nt][2 * half + 1] * s);
            }
        }
    }
}

// ---------------------------------------------------------------------------
// Final projection: out = O @ (Wo_h + Wo_l) + bias, fp16 2-term, fp32 out.
// Block 128x128, 2-stage cp.async (stage = 3 planes x 16KB = 48KB).
// ---------------------------------------------------------------------------
#define GO_SA  0
#define GO_BH  16384
#define GO_BL  32768
#define GO_STAGE 49152
#define GO_SMEM  (2 * GO_STAGE)

__global__ __launch_bounds__(256)
void gemm_out(const float* __restrict__ bias, float* __restrict__ Cout)
{
    extern __shared__ char smem[];
    const uint32_t sb = smem_to_u32(smem);

    const int tid  = threadIdx.x;
    const int wid  = tid >> 5;
    const int lane = tid & 31;
    const int warp_m = wid >> 2;
    const int warp_n = wid & 3;
    const int rowBase = blockIdx.y * 128;
    const int colBase = blockIdx.x * 128;

    float c[4][4][4];
#pragma unroll
    for (int i = 0; i < 4; ++i)
#pragma unroll
        for (int j = 0; j < 4; ++j)
#pragma unroll
            for (int e = 0; e < 4; ++e) c[i][j][e] = 0.f;

    uint32_t aAddr[4], maskA[4];
    {
        int r = lane & 15, hf = lane >> 4;
#pragma unroll
        for (int mt = 0; mt < 4; ++mt) {
            uint32_t rb = (uint32_t)((warp_m * 64 + mt * 16 + r) * 128 + hf * 16);
            maskA[mt] = (rb >> 3) & 0x70;
            aAddr[mt] = rb;
        }
    }
    uint32_t bAddr[2], maskB[2];
    {
        int rn = ((lane >> 4) << 3) + (lane & 7);
        int hf = (lane >> 3) & 1;
#pragma unroll
        for (int nt2 = 0; nt2 < 2; ++nt2) {
            uint32_t rb = (uint32_t)((warp_n * 32 + nt2 * 16 + rn) * 128 + hf * 16);
            maskB[nt2] = (rb >> 3) & 0x70;
            bAddr[nt2] = rb;
        }
    }

    auto load_stage = [&](int st, int kc) {
        uint32_t base = sb + st * GO_STAGE;
#pragma unroll
        for (int it = 0; it < 4; ++it) {
            int unit = it * 256 + tid;
            int row = unit >> 3, seg = unit & 7;
            uint32_t off = SWZ((uint32_t)(row * 128 + seg * 16));
            size_t ga = (size_t)(rowBase + row) * 512 + kc * 64 + seg * 8;
            size_t gb = (size_t)(colBase + row) * 512 + kc * 64 + seg * 8;
            cpa16(base + GO_SA + off, g_of + ga);
            cpa16(base + GO_BH + off, g_woh + gb);
            cpa16(base + GO_BL + off, g_wol + gb);
        }
    };

    load_stage(0, 0);
    CP_COMMIT();

    for (int kc = 0; kc < 8; ++kc) {
        if (kc + 1 < 8) {
            load_stage((kc + 1) & 1, kc + 1);
            CP_COMMIT();
            CP_WAIT(1);
        } else {
            CP_WAIT(0);
        }
        __syncthreads();

        const uint32_t stb = sb + (kc & 1) * GO_STAGE;
#pragma unroll
        for (int ks = 0; ks < 4; ++ks) {
            uint32_t af[4][4], bh[4][2], bl[4][2];
#pragma unroll
            for (int mt = 0; mt < 4; ++mt)
                ldsm4(af[mt], stb + GO_SA + ((aAddr[mt] + ks * 32) ^ maskA[mt]));
#pragma unroll
            for (int nt2 = 0; nt2 < 2; ++nt2) {
                uint32_t o = ((bAddr[nt2] + ks * 32) ^ maskB[nt2]);
                uint32_t t4[4];
                ldsm4(t4, stb + GO_BH + o);
                bh[2 * nt2][0] = t4[0]; bh[2 * nt2][1] = t4[1];
                bh[2 * nt2 + 1][0] = t4[2]; bh[2 * nt2 + 1][1] = t4[3];
                ldsm4(t4, stb + GO_BL + o);
                bl[2 * nt2][0] = t4[0]; bl[2 * nt2][1] = t4[1];
                bl[2 * nt2 + 1][0] = t4[2]; bl[2 * nt2 + 1][1] = t4[3];
            }
#pragma unroll
            for (int mt = 0; mt < 4; ++mt)
#pragma unroll
                for (int nt = 0; nt < 4; ++nt) {
                    mma16816h(c[mt][nt], af[mt], bh[nt]);
                    mma16816h(c[mt][nt], af[mt], bl[nt]);
                }
        }
        __syncthreads();
    }

    const int r0 = (lane >> 2);
    const int c2 = 2 * (lane & 3);
#pragma unroll
    for (int mt = 0; mt < 4; ++mt) {
#pragma unroll
        for (int nt = 0; nt < 4; ++nt) {
            int row = rowBase + warp_m * 64 + mt * 16 + r0;
            int col = colBase + warp_n * 32 + nt * 8 + c2;
            float2 bv = *(const float2*)&bias[col];
            float* p0 = Cout + (size_t)row * 512 + col;
            *(float2*)p0 = make_float2(c[mt][nt][0] + bv.x, c[mt][nt][1] + bv.y);
            float* p1 = Cout + (size_t)(row + 8) * 512 + col;
            *(float2*)p1 = make_float2(c[mt][nt][2] + bv.x, c[mt][nt][3] + bv.y);
        }
    }
}

// ---------------------------------------------------------------------------
// Flash attention: BM=256 (8 warps x 32 q-rows, 2 row-groups of 16/warp),
// KV tiles 64, 256 threads, 2-stage cp.async. Single fp16 MMA, log2 softmax
// with warp-vote rescale skip. O written as fp16.
// smem: Q 32K | stage0 16K | stage1 16K = 64 KB.
// ---------------------------------------------------------------------------
#define AT_Q 0
#define AT_ST0 32768
#define AT_STAGE 16384
#define KV_K 0
#define KV_V 8192
#define AT_SMEM (AT_ST0 + 2 * AT_STAGE)

__global__ __launch_bounds__(256)
void attn_mma()
{
    extern __shared__ char smem[];
    const uint32_t sb = smem_to_u32(smem);
    const int tid = threadIdx.x, wid = tid >> 5, lane = tid & 31;
    const int bh = blockIdx.y, qtile = blockIdx.x;

    const size_t bhoff = (size_t)bh * NN * DD;

    auto load_kv = [&](int st, int jt) {
        uint32_t base = sb + AT_ST0 + st * AT_STAGE;
        const size_t kvoff = bhoff + (size_t)jt * 64 * DD;
#pragma unroll
        for (int i = 0; i < 2; ++i) {
            int unit = i * 256 + tid;        // 512 units per plane
            int row = unit >> 3, seg = unit & 7;
            uint32_t off = (uint32_t)(row * 128 + ((seg * 16) ^ ((row & 7) << 4)));
            size_t g = kvoff + row * 64 + seg * 8;
            cpa16(base + KV_K + off, g_kf + g);
            cpa16(base + KV_V + off, g_vf + g);
        }
    };

    load_kv(0, 0);
    CP_COMMIT();

    // stage Q (256x64 fp16)
    const size_t qoff = bhoff + (size_t)qtile * 256 * DD;
#pragma unroll
    for (int i = 0; i < 8; ++i) {
        int unit = i * 256 + tid;           // 2048 units
        int row = unit >> 3, seg = unit & 7;
        uint32_t off = (uint32_t)(row * 128 + ((seg * 16) ^ ((row & 7) << 4)));
        *(uint4*)(smem + AT_Q + off) = *(const uint4*)(g_qf + qoff + row * 64 + seg * 8);
    }
    __syncthreads();

    // per-warp Q A-fragments: 2 row-groups of 16 rows (rows wid*32 .. +31)
    uint32_t qh[2][4][4];
    {
        int r = lane & 15, hf = lane >> 4;
#pragma unroll
        for (int rg = 0; rg < 2; ++rg) {
            int row = wid * 32 + rg * 16 + r;
            uint32_t base = (uint32_t)(row * 128);
            uint32_t msk = (uint32_t)((row & 7) << 4);
#pragma unroll
            for (int ks = 0; ks < 4; ++ks)
                ldsm4(qh[rg][ks], sb + AT_Q + base + (uint32_t)((hf * 16 + ks * 32) ^ (int)msk));
        }
    }

    const int rnk = ((lane >> 4) << 3) + (lane & 7);
    const int hfk = (lane >> 3) & 1;
    const int jj  = lane & 15;
    const int dd8 = ((lane >> 4) & 1) * 8;

    float m[2][2], l[2][2];
#pragma unroll
    for (int rg = 0; rg < 2; ++rg) {
        m[rg][0] = -1e30f; m[rg][1] = -1e30f;
        l[rg][0] = 0.f;    l[rg][1] = 0.f;
    }
    float o[2][8][4];
#pragma unroll
    for (int rg = 0; rg < 2; ++rg)
#pragma unroll
        for (int t = 0; t < 8; ++t)
#pragma unroll
            for (int e = 0; e < 4; ++e) o[rg][t][e] = 0.f;

    for (int jt = 0; jt < NN / 64; ++jt) {
        if (jt + 1 < NN / 64) {
            load_kv((jt + 1) & 1, jt + 1);
            CP_COMMIT();
            CP_WAIT(1);
        } else {
            CP_WAIT(0);
        }
        __syncthreads();

        const uint32_t stb = sb + AT_ST0 + (jt & 1) * AT_STAGE;

        // ---- S = Q K^T (both row-groups share each K fragment)
        float c[2][8][4];
#pragma unroll
        for (int rg = 0; rg < 2; ++rg)
#pragma unroll
            for (int t = 0; t < 8; ++t)
#pragma unroll
                for (int e = 0; e < 4; ++e) c[rg][t][e] = 0.f;

#pragma unroll
        for (int ks = 0; ks < 4; ++ks) {
            uint32_t kf[4][4];
#pragma unroll
            for (int nt2 = 0; nt2 < 4; ++nt2) {
                int row = nt2 * 16 + rnk;
                uint32_t koff = (uint32_t)(row * 128)
                              + (uint32_t)((hfk * 16 + ks * 32) ^ ((row & 7) << 4));
                ldsm4(kf[nt2], stb + KV_K + koff);
            }
#pragma unroll
            for (int nt2 = 0; nt2 < 4; ++nt2) {
                uint32_t b0[2] = { kf[nt2][0], kf[nt2][1] };
                uint32_t b1[2] = { kf[nt2][2], kf[nt2][3] };
#pragma unroll
                for (int rg = 0; rg < 2; ++rg) {
                    mma16816h(c[rg][2 * nt2 + 0], qh[rg][ks], b0);
                    mma16816h(c[rg][2 * nt2 + 1], qh[rg][ks], b1);
                }
            }
        }

        // ---- online softmax (base-2) per row-group, vote-skip rescale
#pragma unroll
        for (int rg = 0; rg < 2; ++rg) {
            float mx0 = -1e30f, mx1 = -1e30f;
#pragma unroll
            for (int t = 0; t < 8; ++t) {
                mx0 = fmaxf(mx0, fmaxf(c[rg][t][0], c[rg][t][1]));
                mx1 = fmaxf(mx1, fmaxf(c[rg][t][2], c[rg][t][3]));
            }
            mx0 = fmaxf(mx0, __shfl_xor_sync(0xffffffffu, mx0, 1));
            mx0 = fmaxf(mx0, __shfl_xor_sync(0xffffffffu, mx0, 2));
            mx1 = fmaxf(mx1, __shfl_xor_sync(0xffffffffu, mx1, 1));
            mx1 = fmaxf(mx1, __shfl_xor_sync(0xffffffffu, mx1, 2));

            bool nochange = (mx0 <= m[rg][0]) && (mx1 <= m[rg][1]);
            if (!__all_sync(0xffffffffu, nochange)) {
                float nm0 = fmaxf(m[rg][0], mx0), nm1 = fmaxf(m[rg][1], mx1);
                float cr0 = exp2f(m[rg][0] - nm0), cr1 = exp2f(m[rg][1] - nm1);
                m[rg][0] = nm0; m[rg][1] = nm1;
                l[rg][0] *= cr0; l[rg][1] *= cr1;
#pragma unroll
                for (int t = 0; t < 8; ++t) {
                    o[rg][t][0] *= cr0; o[rg][t][1] *= cr0;
                    o[rg][t][2] *= cr1; o[rg][t][3] *= cr1;
                }
            }
        }

        // ---- O += P V (both row-groups share each V fragment)
#pragma unroll
        for (int ks = 0; ks < 4; ++ks) {
            uint32_t aP[2][4];
#pragma unroll
            for (int rg = 0; rg < 2; ++rg) {
#pragma unroll
                for (int half = 0; half < 2; ++half) {
                    int t = 2 * ks + half;
                    float p0 = exp2f(c[rg][t][0] - m[rg][0]);
                    float p1 = exp2f(c[rg][t][1] - m[rg][0]);
                    float p2 = exp2f(c[rg][t][2] - m[rg][1]);
                    float p3 = exp2f(c[rg][t][3] - m[rg][1]);
                    l[rg][0] += p0 + p1;
                    l[rg][1] += p2 + p3;
                    aP[rg][half ? 2 : 0] = hf2pack(p0, p1);
                    aP[rg][half ? 3 : 1] = hf2pack(p2, p3);
                }
            }
            int row = ks * 16 + jj;
            uint32_t rbase = (uint32_t)(row * 128);
            uint32_t msk = (uint32_t)((row & 7) << 4);
#pragma unroll
            for (int dt2 = 0; dt2 < 4; ++dt2) {
                uint32_t off = rbase + (uint32_t)(((dt2 * 16 + dd8) * 2) ^ (int)msk);
                uint32_t v4[4];
                ldsm4t(v4, stb + KV_V + off);
                uint32_t b0[2] = { v4[0], v4[1] };
                uint32_t b1[2] = { v4[2], v4[3] };
#pragma unroll
                for (int rg = 0; rg < 2; ++rg) {
                    mma16816h(o[rg][2 * dt2 + 0], aP[rg], b0);
                    mma16816h(o[rg][2 * dt2 + 1], aP[rg], b1);
                }
            }
        }
        __syncthreads();
    }

    // quad-reduce l (o already holds the full row sum via MMA k-reduction)
#pragma unroll
    for (int rg = 0; rg < 2; ++rg) {
        l[rg][0] += __shfl_xor_sync(0xffffffffu, l[rg][0], 1);
        l[rg][0] += __shfl_xor_sync(0xffffffffu, l[rg][0], 2);
        l[rg][1] += __shfl_xor_sync(0xffffffffu, l[rg][1], 1);
        l[rg][1] += __shfl_xor_sync(0xffffffffu, l[rg][1], 2);
    }

    // ---- epilogue: write fp16 O at [b, n, h*64+d]
    const int b = bh >> 3, h = bh & 7;
    const int colb = h * 64 + 2 * (lane & 3);
#pragma unroll
    for (int rg = 0; rg < 2; ++rg) {
        const int gr = wid * 32 + rg * 16 + (lane >> 2);
        const int n0 = qtile * 256 + gr;
        const float inv0 = 1.f / l[rg][0], inv1 = 1.f / l[rg][1];
#pragma unroll
        for (int t = 0; t < 8; ++t) {
            const int d = t * 8;
            {
                size_t idx = (((size_t)(b * NN + n0) * INNERR) + colb + d) >> 1;
                ((uint32_t*)g_of)[idx] = hf2pack(o[rg][t][0] * inv0, o[rg][t][1] * inv0);
            }
            {
                size_t idx = (((size_t)(b * NN + n0 + 8) * INNERR) + colb + d) >> 1;
                ((uint32_t*)g_of)[idx] = hf2pack(o[rg][t][2] * inv1, o[rg][t][3] * inv1);
            }
        }
    }
}

// ---------------------------------------------------------------------------
extern "C" void kernel_launch(void* const* d_in, const int* in_sizes, int n_in,
                              void* d_out, int out_size)
{
    const float* x  = (const float*)d_in[0];
    const float* m  = (const float*)d_in[1];
    const float* Wq = (const float*)d_in[2];
    const float* Wk = (const float*)d_in[3];
    const float* Wv = (const float*)d_in[4];
    const float* Wo = (const float*)d_in[5];
    const float* bo = (const float*)d_in[6];
    float* out = (float*)d_out;

    cudaFuncSetAttribute(attn_mma, cudaFuncAttributeMaxDynamicSharedMemorySize, AT_SMEM);
    cudaFuncSetAttribute(gemm_qkv, cudaFuncAttributeMaxDynamicSharedMemorySize, GF_SMEM);
    cudaFuncSetAttribute(gemm_out, cudaFuncAttributeMaxDynamicSharedMemorySize, GO_SMEM);

    cvtA<<<dim3(8192, 2), 256>>>(x, m);                       // 0
    cvtW<<<dim3(16, 16, 4), dim3(32, 32)>>>(Wq, Wk, Wv, Wo);  // 1
    gemm_qkv<<<dim3(12, 128), 256, GF_SMEM>>>();              // 2
    attn_mma<<<dim3(NN / 256, BB * HH), 256, AT_SMEM>>>();    // 3 <- profiled
    gemm_out<<<dim3(4, 128), 256, GO_SMEM>>>(bo, out);        // 4
}

// round 17
// speedup vs baseline: 1.6356x; 1.6356x over previous
#include <cuda_runtime.h>
#include <cuda_bf16.h>
#include <cuda_fp16.h>
#include <cstdint>

// Problem constants
#define BB    8
#define NN    2048
#define DIMM  512
#define HH    8
#define DD    64
#define INNERR 512
#define NSCALE 0.044194173824159216f   // 512^-0.5
#define LOG2E  1.4426950408889634f
#define QSCALE (NSCALE * LOG2E)        // folded so S is in log2 domain

// ---- warp MMA helpers (sm_80+ baseline; no arch-'a' gating) ----
__device__ __forceinline__ void ldsm4(uint32_t* r, uint32_t addr) {
    asm volatile("ldmatrix.sync.aligned.m8n8.x4.shared.b16 {%0,%1,%2,%3}, [%4];"
                 : "=r"(r[0]), "=r"(r[1]), "=r"(r[2]), "=r"(r[3]) : "r"(addr));
}
__device__ __forceinline__ void ldsm4t(uint32_t* r, uint32_t addr) {
    asm volatile("ldmatrix.sync.aligned.m8n8.x4.trans.shared.b16 {%0,%1,%2,%3}, [%4];"
                 : "=r"(r[0]), "=r"(r[1]), "=r"(r[2]), "=r"(r[3]) : "r"(addr));
}
__device__ __forceinline__ void mma16816h(float* c, const uint32_t* a, const uint32_t* b) {
    asm volatile("mma.sync.aligned.m16n8k16.row.col.f32.f16.f16.f32 "
                 "{%0,%1,%2,%3}, {%4,%5,%6,%7}, {%8,%9}, {%0,%1,%2,%3};"
                 : "+f"(c[0]), "+f"(c[1]), "+f"(c[2]), "+f"(c[3])
                 : "r"(a[0]), "r"(a[1]), "r"(a[2]), "r"(a[3]), "r"(b[0]), "r"(b[1]));
}
__device__ __forceinline__ uint32_t smem_to_u32(const void* p) {
    uint32_t a;
    asm("{ .reg .u64 t; cvta.to.shared.u64 t, %1; cvt.u32.u64 %0, t; }"
        : "=r"(a) : "l"(p));
    return a;
}
// ---- cp.async (LDGSTS) ----
__device__ __forceinline__ void cpa16(uint32_t dst, const void* src) {
    asm volatile("cp.async.cg.shared.global [%0], [%1], 16;" :: "r"(dst), "l"(src));
}
#define CP_COMMIT() asm volatile("cp.async.commit_group;" ::: "memory")
#define CP_WAIT(N)  asm volatile("cp.async.wait_group %0;" :: "n"(N) : "memory")

#define SWZ(off) ((off) ^ (((off) >> 3) & 0x70))

__device__ __forceinline__ uint32_t hf2pack(float lo, float hi) {
    __half2 t = __floats2half2_rn(lo, hi);
    return *reinterpret_cast<uint32_t*>(&t);
}

// =========================== scratch (device globals only) =================
#define ACNT ((size_t)16384 * 512)
__device__ unsigned short g_xf[ACNT];               // x fp16
__device__ unsigned short g_mf[ACNT];               // m fp16
__device__ unsigned short g_of[ACNT];               // attention out fp16 [b,n,(h d)]
#define QKV ((size_t)BB * HH * NN * DD)
__device__ unsigned short g_qf[QKV];                // Q*qscale fp16 [b,h,n,d]
__device__ unsigned short g_kf[QKV];                // K fp16
__device__ unsigned short g_vf[QKV];                // V fp16
#define WCNT ((size_t)512 * 512)
__device__ unsigned short g_wqf[WCNT];              // Wq^T fp16
__device__ unsigned short g_wkf[WCNT];              // Wk^T fp16
__device__ unsigned short g_wvf[WCNT];              // Wv^T fp16
__device__ unsigned short g_woh[WCNT], g_wol[WCNT]; // Wo^T fp16 hi/lo

// ---------------------------------------------------------------------------
// cvtA: fp32 [16384,512] -> fp16. blockIdx.y selects x / m.
// ---------------------------------------------------------------------------
__global__ __launch_bounds__(256)
void cvtA(const float* __restrict__ x, const float* __restrict__ m)
{
    const float* src = blockIdx.y ? m : x;
    unsigned short* d = blockIdx.y ? g_mf : g_xf;
    size_t i4 = (size_t)blockIdx.x * 256 + threadIdx.x;
    float4 v = ((const float4*)src)[i4];
    uint2 o;
    o.x = hf2pack(v.x, v.y);
    o.y = hf2pack(v.z, v.w);
    ((uint2*)d)[i4] = o;
}

// ---------------------------------------------------------------------------
// cvtW: all 4 weights, blockIdx.z selects. z<3 -> fp16 transposed plane;
// z==3 -> Wo fp16 hi/lo transposed planes.
// ---------------------------------------------------------------------------
__global__ __launch_bounds__(1024)
void cvtW(const float* __restrict__ Wq, const float* __restrict__ Wk,
          const float* __restrict__ Wv, const float* __restrict__ Wo)
{
    const int z = blockIdx.z;
    const float* W = (z == 0) ? Wq : (z == 1) ? Wk : (z == 2) ? Wv : Wo;
    __shared__ float tile[32][33];
    int k = blockIdx.y * 32 + threadIdx.y;
    int n = blockIdx.x * 32 + threadIdx.x;
    tile[threadIdx.y][threadIdx.x] = W[(size_t)k * 512 + n];
    __syncthreads();
    int nn = blockIdx.x * 32 + threadIdx.y;
    int kk = blockIdx.y * 32 + threadIdx.x;
    float v = tile[threadIdx.x][threadIdx.y];
    size_t idx = (size_t)nn * 512 + kk;
    if (z < 3) {
        unsigned short* d = (z == 0) ? g_wqf : (z == 1) ? g_wkf : g_wvf;
        d[idx] = __half_as_ushort(__float2half_rn(v));
    } else {
        __half hh = __float2half_rn(v);
        float r = v - __half2float(hh);
        g_woh[idx] = __half_as_ushort(hh);
        g_wol[idx] = __half_as_ushort(__float2half_rn(r));
    }
}

// ---------------------------------------------------------------------------
// Fused QKV projection GEMM: grid (12, 128).
// col-blocks 0-3: Q = x @ Wq * QSCALE; 4-7: K = m @ Wk; 8-11: V = m @ Wv.
// Block 128x128, 8 warps, 2-stage cp.async (stage = 32KB). fp16 out, head-split.
// ---------------------------------------------------------------------------
#define GF_SA 0
#define GF_SB 16384
#define GF_STAGE 32768
#define GF_SMEM (2 * GF_STAGE)

__global__ __launch_bounds__(256)
void gemm_qkv()
{
    const int sel = blockIdx.x >> 2;        // 0=Q 1=K 2=V
    const int cb  = blockIdx.x & 3;         // col block within 512
    const unsigned short* A = (sel == 0) ? g_xf : g_mf;
    const unsigned short* B = (sel == 0) ? g_wqf : (sel == 1) ? g_wkf : g_wvf;
    unsigned short* Cf = (sel == 0) ? g_qf : (sel == 1) ? g_kf : g_vf;

    extern __shared__ char smem[];
    const uint32_t sb = smem_to_u32(smem);

    const int tid  = threadIdx.x;
    const int wid  = tid >> 5;
    const int lane = tid & 31;
    const int warp_m = wid >> 2;
    const int warp_n = wid & 3;
    const int rowBase = blockIdx.y * 128;
    const int colBase = cb * 128;

    float c[4][4][4];
#pragma unroll
    for (int i = 0; i < 4; ++i)
#pragma unroll
        for (int j = 0; j < 4; ++j)
#pragma unroll
            for (int e = 0; e < 4; ++e) c[i][j][e] = 0.f;

    uint32_t aAddr[4], maskA[4];
    {
        int r = lane & 15, hf = lane >> 4;
#pragma unroll
        for (int mt = 0; mt < 4; ++mt) {
            uint32_t rb = (uint32_t)((warp_m * 64 + mt * 16 + r) * 128 + hf * 16);
            maskA[mt] = (rb >> 3) & 0x70;
            aAddr[mt] = rb;
        }
    }
    uint32_t bAddr[2], maskB[2];
    {
        int rn = ((lane >> 4) << 3) + (lane & 7);
        int hf = (lane >> 3) & 1;
#pragma unroll
        for (int nt2 = 0; nt2 < 2; ++nt2) {
            uint32_t rb = (uint32_t)((warp_n * 32 + nt2 * 16 + rn) * 128 + hf * 16);
            maskB[nt2] = (rb >> 3) & 0x70;
            bAddr[nt2] = rb;
        }
    }

    auto load_stage = [&](int st, int kc) {
        uint32_t base = sb + st * GF_STAGE;
#pragma unroll
        for (int it = 0; it < 4; ++it) {
            int unit = it * 256 + tid;
            int row = unit >> 3, seg = unit & 7;
            uint32_t off = SWZ((uint32_t)(row * 128 + seg * 16));
            cpa16(base + GF_SA + off, A + (size_t)(rowBase + row) * 512 + kc * 64 + seg * 8);
            cpa16(base + GF_SB + off, B + (size_t)(colBase + row) * 512 + kc * 64 + seg * 8);
        }
    };

    load_stage(0, 0);
    CP_COMMIT();

    for (int kc = 0; kc < 8; ++kc) {
        if (kc + 1 < 8) {
            load_stage((kc + 1) & 1, kc + 1);
            CP_COMMIT();
            CP_WAIT(1);
        } else {
            CP_WAIT(0);
        }
        __syncthreads();

        const uint32_t stb = sb + (kc & 1) * GF_STAGE;
#pragma unroll
        for (int ks = 0; ks < 4; ++ks) {
            uint32_t af[4][4], bf[4][2];
#pragma unroll
            for (int mt = 0; mt < 4; ++mt)
                ldsm4(af[mt], stb + GF_SA + ((aAddr[mt] + ks * 32) ^ maskA[mt]));
#pragma unroll
            for (int nt2 = 0; nt2 < 2; ++nt2) {
                uint32_t t4[4];
                ldsm4(t4, stb + GF_SB + ((bAddr[nt2] + ks * 32) ^ maskB[nt2]));
                bf[2 * nt2][0] = t4[0]; bf[2 * nt2][1] = t4[1];
                bf[2 * nt2 + 1][0] = t4[2]; bf[2 * nt2 + 1][1] = t4[3];
            }
#pragma unroll
            for (int mt = 0; mt < 4; ++mt)
#pragma unroll
                for (int nt = 0; nt < 4; ++nt)
                    mma16816h(c[mt][nt], af[mt], bf[nt]);
        }
        __syncthreads();
    }

    const int r0 = (lane >> 2);
    const int c2 = 2 * (lane & 3);
    const float s = (sel == 0) ? QSCALE : 1.f;
#pragma unroll
    for (int mt = 0; mt < 4; ++mt) {
#pragma unroll
        for (int nt = 0; nt < 4; ++nt) {
            int row = rowBase + warp_m * 64 + mt * 16 + r0;
            int col = colBase + warp_n * 32 + nt * 8 + c2;
            const int h = col >> 6, d0 = col & 63;
#pragma unroll
            for (int half = 0; half < 2; ++half) {
                const int rw = row + half * 8;
                const int b = rw >> 11, n = rw & 2047;
                size_t idx = (((size_t)(b * HH + h) * NN + n) * DD + d0) >> 1;
                ((uint32_t*)Cf)[idx] = hf2pack(c[mt][nt][2 * half + 0] * s,
                                               c[mt][nt][2 * half + 1] * s);
            }
        }
    }
}

// ---------------------------------------------------------------------------
// Final projection: out = O @ (Wo_h + Wo_l) + bias, fp16 2-term, fp32 out.
// Block 128x128, 2-stage cp.async (stage = 3 planes x 16KB = 48KB).
// ---------------------------------------------------------------------------
#define GO_SA  0
#define GO_BH  16384
#define GO_BL  32768
#define GO_STAGE 49152
#define GO_SMEM  (2 * GO_STAGE)

__global__ __launch_bounds__(256)
void gemm_out(const float* __restrict__ bias, float* __restrict__ Cout)
{
    extern __shared__ char smem[];
    const uint32_t sb = smem_to_u32(smem);

    const int tid  = threadIdx.x;
    const int wid  = tid >> 5;
    const int lane = tid & 31;
    const int warp_m = wid >> 2;
    const int warp_n = wid & 3;
    const int rowBase = blockIdx.y * 128;
    const int colBase = blockIdx.x * 128;

    float c[4][4][4];
#pragma unroll
    for (int i = 0; i < 4; ++i)
#pragma unroll
        for (int j = 0; j < 4; ++j)
#pragma unroll
            for (int e = 0; e < 4; ++e) c[i][j][e] = 0.f;

    uint32_t aAddr[4], maskA[4];
    {
        int r = lane & 15, hf = lane >> 4;
#pragma unroll
        for (int mt = 0; mt < 4; ++mt) {
            uint32_t rb = (uint32_t)((warp_m * 64 + mt * 16 + r) * 128 + hf * 16);
            maskA[mt] = (rb >> 3) & 0x70;
            aAddr[mt] = rb;
        }
    }
    uint32_t bAddr[2], maskB[2];
    {
        int rn = ((lane >> 4) << 3) + (lane & 7);
        int hf = (lane >> 3) & 1;
#pragma unroll
        for (int nt2 = 0; nt2 < 2; ++nt2) {
            uint32_t rb = (uint32_t)((warp_n * 32 + nt2 * 16 + rn) * 128 + hf * 16);
            maskB[nt2] = (rb >> 3) & 0x70;
            bAddr[nt2] = rb;
        }
    }

    auto load_stage = [&](int st, int kc) {
        uint32_t base = sb + st * GO_STAGE;
#pragma unroll
        for (int it = 0; it < 4; ++it) {
            int unit = it * 256 + tid;
            int row = unit >> 3, seg = unit & 7;
            uint32_t off = SWZ((uint32_t)(row * 128 + seg * 16));
            size_t ga = (size_t)(rowBase + row) * 512 + kc * 64 + seg * 8;
            size_t gb = (size_t)(colBase + row) * 512 + kc * 64 + seg * 8;
            cpa16(base + GO_SA + off, g_of + ga);
            cpa16(base + GO_BH + off, g_woh + gb);
            cpa16(base + GO_BL + off, g_wol + gb);
        }
    };

    load_stage(0, 0);
    CP_COMMIT();

    for (int kc = 0; kc < 8; ++kc) {
        if (kc + 1 < 8) {
            load_stage((kc + 1) & 1, kc + 1);
            CP_COMMIT();
            CP_WAIT(1);
        } else {
            CP_WAIT(0);
        }
        __syncthreads();

        const uint32_t stb = sb + (kc & 1) * GO_STAGE;
#pragma unroll
        for (int ks = 0; ks < 4; ++ks) {
            uint32_t af[4][4], bh[4][2], bl[4][2];
#pragma unroll
            for (int mt = 0; mt < 4; ++mt)
                ldsm4(af[mt], stb + GO_SA + ((aAddr[mt] + ks * 32) ^ maskA[mt]));
#pragma unroll
            for (int nt2 = 0; nt2 < 2; ++nt2) {
                uint32_t o = ((bAddr[nt2] + ks * 32) ^ maskB[nt2]);
                uint32_t t4[4];
                ldsm4(t4, stb + GO_BH + o);
                bh[2 * nt2][0] = t4[0]; bh[2 * nt2][1] = t4[1];
                bh[2 * nt2 + 1][0] = t4[2]; bh[2 * nt2 + 1][1] = t4[3];
                ldsm4(t4, stb + GO_BL + o);
                bl[2 * nt2][0] = t4[0]; bl[2 * nt2][1] = t4[1];
                bl[2 * nt2 + 1][0] = t4[2]; bl[2 * nt2 + 1][1] = t4[3];
            }
#pragma unroll
            for (int mt = 0; mt < 4; ++mt)
#pragma unroll
                for (int nt = 0; nt < 4; ++nt) {
                    mma16816h(c[mt][nt], af[mt], bh[nt]);
                    mma16816h(c[mt][nt], af[mt], bl[nt]);
                }
        }
        __syncthreads();
    }

    const int r0 = (lane >> 2);
    const int c2 = 2 * (lane & 3);
#pragma unroll
    for (int mt = 0; mt < 4; ++mt) {
#pragma unroll
        for (int nt = 0; nt < 4; ++nt) {
            int row = rowBase + warp_m * 64 + mt * 16 + r0;
            int col = colBase + warp_n * 32 + nt * 8 + c2;
            float2 bv = *(const float2*)&bias[col];
            float* p0 = Cout + (size_t)row * 512 + col;
            *(float2*)p0 = make_float2(c[mt][nt][0] + bv.x, c[mt][nt][1] + bv.y);
            float* p1 = Cout + (size_t)(row + 8) * 512 + col;
            *(float2*)p1 = make_float2(c[mt][nt][2] + bv.x, c[mt][nt][3] + bv.y);
        }
    }
}

// ---------------------------------------------------------------------------
// Flash attention (round-15 shape + vote-skip + 3-stage pipeline):
// 4 warps x 32 q-rows (2 row-groups of 16/warp), BM=128, KV tiles 64,
// 128 threads, 2 CTAs/SM. Single fp16 MMA, log2 softmax.
// smem: Q 16K | 3 KV stages x 16K = 64 KB.
// ---------------------------------------------------------------------------
#define AT_Q 0
#define AT_ST0 16384
#define AT_STAGE 16384
#define KV_K 0
#define KV_V 8192
#define AT_SMEM (AT_ST0 + 3 * AT_STAGE)
#define NTILES (NN / 64)

__global__ __launch_bounds__(128)
void attn_mma()
{
    extern __shared__ char smem[];
    const uint32_t sb = smem_to_u32(smem);
    const int tid = threadIdx.x, wid = tid >> 5, lane = tid & 31;
    const int bh = blockIdx.y, qtile = blockIdx.x;

    const size_t bhoff = (size_t)bh * NN * DD;

    auto load_kv = [&](int st, int jt) {
        uint32_t base = sb + AT_ST0 + st * AT_STAGE;
        const size_t kvoff = bhoff + (size_t)jt * 64 * DD;
#pragma unroll
        for (int i = 0; i < 4; ++i) {
            int unit = i * 128 + tid;        // 512 units per plane
            int row = unit >> 3, seg = unit & 7;
            uint32_t off = (uint32_t)(row * 128 + ((seg * 16) ^ ((row & 7) << 4)));
            size_t g = kvoff + row * 64 + seg * 8;
            cpa16(base + KV_K + off, g_kf + g);
            cpa16(base + KV_V + off, g_vf + g);
        }
    };

    load_kv(0, 0);
    CP_COMMIT();
    load_kv(1, 1);
    CP_COMMIT();

    const size_t qoff = bhoff + (size_t)qtile * 128 * DD;
#pragma unroll
    for (int i = 0; i < 8; ++i) {
        int unit = i * 128 + tid;           // 1024 units
        int row = unit >> 3, seg = unit & 7;
        uint32_t off = (uint32_t)(row * 128 + ((seg * 16) ^ ((row & 7) << 4)));
        *(uint4*)(smem + AT_Q + off) = *(const uint4*)(g_qf + qoff + row * 64 + seg * 8);
    }
    __syncthreads();

    // per-warp Q A-fragments: 2 row-groups of 16 rows
    uint32_t qh[2][4][4];
    {
        int r = lane & 15, hf = lane >> 4;
#pragma unroll
        for (int rg = 0; rg < 2; ++rg) {
            int row = wid * 32 + rg * 16 + r;
            uint32_t base = (uint32_t)(row * 128);
            uint32_t msk = (uint32_t)((row & 7) << 4);
#pragma unroll
            for (int ks = 0; ks < 4; ++ks)
                ldsm4(qh[rg][ks], sb + AT_Q + base + (uint32_t)((hf * 16 + ks * 32) ^ (int)msk));
        }
    }

    const int rnk = ((lane >> 4) << 3) + (lane & 7);
    const int hfk = (lane >> 3) & 1;
    const int jj  = lane & 15;
    const int dd8 = ((lane >> 4) & 1) * 8;

    float m[2][2], l[2][2];
#pragma unroll
    for (int rg = 0; rg < 2; ++rg) {
        m[rg][0] = -1e30f; m[rg][1] = -1e30f;
        l[rg][0] = 0.f;    l[rg][1] = 0.f;
    }
    float o[2][8][4];
#pragma unroll
    for (int rg = 0; rg < 2; ++rg)
#pragma unroll
        for (int t = 0; t < 8; ++t)
#pragma unroll
            for (int e = 0; e < 4; ++e) o[rg][t][e] = 0.f;

    int stage = 0;
    for (int jt = 0; jt < NTILES; ++jt) {
        if (jt + 2 < NTILES) {
            // stage (jt+2)%3 was last read at iteration jt-1; freed by the
            // end-of-loop barrier of jt-1.
            load_kv((jt + 2) % 3, jt + 2);
            CP_COMMIT();
            CP_WAIT(2);
        } else if (jt + 1 < NTILES) {
            CP_WAIT(1);
        } else {
            CP_WAIT(0);
        }
        __syncthreads();

        const uint32_t stb = sb + AT_ST0 + stage * AT_STAGE;

        // ---- S = Q K^T (both row-groups share each K fragment)
        float c[2][8][4];
#pragma unroll
        for (int rg = 0; rg < 2; ++rg)
#pragma unroll
            for (int t = 0; t < 8; ++t)
#pragma unroll
                for (int e = 0; e < 4; ++e) c[rg][t][e] = 0.f;

#pragma unroll
        for (int ks = 0; ks < 4; ++ks) {
            uint32_t kf[4][4];
#pragma unroll
            for (int nt2 = 0; nt2 < 4; ++nt2) {
                int row = nt2 * 16 + rnk;
                uint32_t koff = (uint32_t)(row * 128)
                              + (uint32_t)((hfk * 16 + ks * 32) ^ ((row & 7) << 4));
                ldsm4(kf[nt2], stb + KV_K + koff);
            }
#pragma unroll
            for (int nt2 = 0; nt2 < 4; ++nt2) {
                uint32_t b0[2] = { kf[nt2][0], kf[nt2][1] };
                uint32_t b1[2] = { kf[nt2][2], kf[nt2][3] };
#pragma unroll
                for (int rg = 0; rg < 2; ++rg) {
                    mma16816h(c[rg][2 * nt2 + 0], qh[rg][ks], b0);
                    mma16816h(c[rg][2 * nt2 + 1], qh[rg][ks], b1);
                }
            }
        }

        // ---- online softmax (base-2) per row-group, vote-skip rescale
#pragma unroll
        for (int rg = 0; rg < 2; ++rg) {
            float mx0 = -1e30f, mx1 = -1e30f;
#pragma unroll
            for (int t = 0; t < 8; ++t) {
                mx0 = fmaxf(mx0, fmaxf(c[rg][t][0], c[rg][t][1]));
                mx1 = fmaxf(mx1, fmaxf(c[rg][t][2], c[rg][t][3]));
            }
            mx0 = fmaxf(mx0, __shfl_xor_sync(0xffffffffu, mx0, 1));
            mx0 = fmaxf(mx0, __shfl_xor_sync(0xffffffffu, mx0, 2));
            mx1 = fmaxf(mx1, __shfl_xor_sync(0xffffffffu, mx1, 1));
            mx1 = fmaxf(mx1, __shfl_xor_sync(0xffffffffu, mx1, 2));

            bool nochange = (mx0 <= m[rg][0]) && (mx1 <= m[rg][1]);
            if (!__all_sync(0xffffffffu, nochange)) {
                float nm0 = fmaxf(m[rg][0], mx0), nm1 = fmaxf(m[rg][1], mx1);
                float cr0 = exp2f(m[rg][0] - nm0), cr1 = exp2f(m[rg][1] - nm1);
                m[rg][0] = nm0; m[rg][1] = nm1;
                l[rg][0] *= cr0; l[rg][1] *= cr1;
#pragma unroll
                for (int t = 0; t < 8; ++t) {
                    o[rg][t][0] *= cr0; o[rg][t][1] *= cr0;
                    o[rg][t][2] *= cr1; o[rg][t][3] *= cr1;
                }
            }
        }

        // ---- O += P V (both row-groups share each V fragment)
#pragma unroll
        for (int ks = 0; ks < 4; ++ks) {
            uint32_t aP[2][4];
#pragma unroll
            for (int rg = 0; rg < 2; ++rg) {
#pragma unroll
                for (int half = 0; half < 2; ++half) {
                    int t = 2 * ks + half;
                    float p0 = exp2f(c[rg][t][0] - m[rg][0]);
                    float p1 = exp2f(c[rg][t][1] - m[rg][0]);
                    float p2 = exp2f(c[rg][t][2] - m[rg][1]);
                    float p3 = exp2f(c[rg][t][3] - m[rg][1]);
                    l[rg][0] += p0 + p1;
                    l[rg][1] += p2 + p3;
                    aP[rg][half ? 2 : 0] = hf2pack(p0, p1);
                    aP[rg][half ? 3 : 1] = hf2pack(p2, p3);
                }
            }
            int row = ks * 16 + jj;
            uint32_t rbase = (uint32_t)(row * 128);
            uint32_t msk = (uint32_t)((row & 7) << 4);
#pragma unroll
            for (int dt2 = 0; dt2 < 4; ++dt2) {
                uint32_t off = rbase + (uint32_t)(((dt2 * 16 + dd8) * 2) ^ (int)msk);
                uint32_t v4[4];
                ldsm4t(v4, stb + KV_V + off);
                uint32_t b0[2] = { v4[0], v4[1] };
                uint32_t b1[2] = { v4[2], v4[3] };
#pragma unroll
                for (int rg = 0; rg < 2; ++rg) {
                    mma16816h(o[rg][2 * dt2 + 0], aP[rg], b0);
                    mma16816h(o[rg][2 * dt2 + 1], aP[rg], b1);
                }
            }
        }
        __syncthreads();   // stage may be refilled next iteration
        stage = (stage + 1 == 3) ? 0 : stage + 1;
    }

    // quad-reduce l (o already holds the full row sum via MMA k-reduction)
#pragma unroll
    for (int rg = 0; rg < 2; ++rg) {
        l[rg][0] += __shfl_xor_sync(0xffffffffu, l[rg][0], 1);
        l[rg][0] += __shfl_xor_sync(0xffffffffu, l[rg][0], 2);
        l[rg][1] += __shfl_xor_sync(0xffffffffu, l[rg][1], 1);
        l[rg][1] += __shfl_xor_sync(0xffffffffu, l[rg][1], 2);
    }

    // ---- epilogue: write fp16 O at [b, n, h*64+d]
    const int b = bh >> 3, h = bh & 7;
    const int colb = h * 64 + 2 * (lane & 3);
#pragma unroll
    for (int rg = 0; rg < 2; ++rg) {
        const int gr = wid * 32 + rg * 16 + (lane >> 2);
        const int n0 = qtile * 128 + gr;
        const float inv0 = 1.f / l[rg][0], inv1 = 1.f / l[rg][1];
#pragma unroll
        for (int t = 0; t < 8; ++t) {
            const int d = t * 8;
            {
                size_t idx = (((size_t)(b * NN + n0) * INNERR) + colb + d) >> 1;
                ((uint32_t*)g_of)[idx] = hf2pack(o[rg][t][0] * inv0, o[rg][t][1] * inv0);
            }
            {
                size_t idx = (((size_t)(b * NN + n0 + 8) * INNERR) + colb + d) >> 1;
                ((uint32_t*)g_of)[idx] = hf2pack(o[rg][t][2] * inv1, o[rg][t][3] * inv1);
            }
        }
    }
}

// ---------------------------------------------------------------------------
extern "C" void kernel_launch(void* const* d_in, const int* in_sizes, int n_in,
                              void* d_out, int out_size)
{
    const float* x  = (const float*)d_in[0];
    const float* m  = (const float*)d_in[1];
    const float* Wq = (const float*)d_in[2];
    const float* Wk = (const float*)d_in[3];
    const float* Wv = (const float*)d_in[4];
    const float* Wo = (const float*)d_in[5];
    const float* bo = (const float*)d_in[6];
    float* out = (float*)d_out;

    cudaFuncSetAttribute(attn_mma, cudaFuncAttributeMaxDynamicSharedMemorySize, AT_SMEM);
    cudaFuncSetAttribute(gemm_qkv, cudaFuncAttributeMaxDynamicSharedMemorySize, GF_SMEM);
    cudaFuncSetAttribute(gemm_out, cudaFuncAttributeMaxDynamicSharedMemorySize, GO_SMEM);

    cvtA<<<dim3(8192, 2), 256>>>(x, m);                       // 0
    cvtW<<<dim3(16, 16, 4), dim3(32, 32)>>>(Wq, Wk, Wv, Wo);  // 1
    gemm_qkv<<<dim3(12, 128), 256, GF_SMEM>>>();              // 2
    attn_mma<<<dim3(16, BB * HH), 128, AT_SMEM>>>();          // 3 <- profiled
    gemm_out<<<dim3(4, 128), 256, GO_SMEM>>>(bo, out);        // 4
}